// round 11
// baseline (speedup 1.0000x reference)
#include <cuda_runtime.h>
#include <cuda_fp16.h>
#include <cuda_fp8.h>
#include <mma.h>
#include <math.h>
#include <stdint.h>

using namespace nvcuda;

#define NS 305
#define SP 320
#define SPSP (SP * SP)
#define NB 64
#define NT 4096
#define NSTEP 819            // 5-gram supersteps: 1 + 5*819 = 4096 exactly
#define NMAT 256             // 4^4 composite matrices
#define LOG_SCALE_D 8.317766166719343   // log(4096)
#define DITH1 1.0471f        // dither factor for copy 1 (compensated exactly via g_rs)

// ---------------- device globals (zero-initialized) ----------------
__device__ float g_I[SP];
__device__ __align__(16) float g_BmT[4][SP];              // BmT[a][s] = Bm[s][a]
__device__ __align__(16) __half g_A16[SPSP];              // softmax(A), fp16
__device__ __align__(16) __half g_Q16[4][SPSP];           // Q_a = (A Da) A
__device__ __align__(16) __half g_U16[16][SPSP];          // U_cd = (Q_c Dd) A
__device__ __align__(16) __half g_M16[(size_t)NMAT * SPSP];  // M_abcd = (Q_a Db) U_cd
// e5m2, 2 dither copies, 8-col blocked: byte (r,c) at ((r>>5)*40 + (c>>3))*256 + (r&31)*8 + (c&7)
__device__ __align__(16) unsigned char g_S[2ull * NMAT * SPSP];
__device__ __align__(16) float g_rs[2 * NMAT * SP];       // alpha row multiplier 4096/q per copy
__device__ unsigned short g_gram[NB * NSTEP];             // (z<<2)|fold, z in 0..255
__device__ unsigned char g_o0[NB];

__device__ __forceinline__ float warpSum(float x) {
    #pragma unroll
    for (int o = 16; o; o >>= 1) x += __shfl_down_sync(0xffffffffu, x, o);
    return x;
}
__device__ __forceinline__ float warpMax(float x) {
    #pragma unroll
    for (int o = 16; o; o >>= 1) x = fmaxf(x, __shfl_down_sync(0xffffffffu, x, o));
    return x;
}
__device__ __forceinline__ float warpMaxAll(float x) {
    #pragma unroll
    for (int o = 16; o; o >>= 1) x = fmaxf(x, __shfl_xor_sync(0xffffffffu, x, o));
    return x;
}
__device__ __forceinline__ __half2 u2h(uint32_t u) { return *reinterpret_cast<__half2*>(&u); }
__device__ __forceinline__ uint32_t h2u(__half2 h) { return *reinterpret_cast<uint32_t*>(&h); }
__device__ __forceinline__ uint32_t hadd2u(uint32_t a, uint32_t b) {
    return h2u(__hadd2(u2h(a), u2h(b)));
}
__device__ __forceinline__ uint32_t s2u(const void* p) {
    uint32_t a;
    asm("{ .reg .u64 t; cvta.to.shared.u64 t, %1; cvt.u32.u64 %0, t; }" : "=r"(a) : "l"(p));
    return a;
}

// ---------------- setup: I softmax + emission softmax ----------------
__global__ void k_setup(const float* __restrict__ initk, const float* __restrict__ emisk) {
    __shared__ float red[16];
    __shared__ float bval;
    int tid = threadIdx.x, wid = tid >> 5, lane = tid & 31;
    const int nw = 16;
    float v = (tid < NS) ? initk[tid] : -1e30f;
    float m = warpMax(v);
    if (lane == 0) red[wid] = m;
    __syncthreads();
    if (tid == 0) { float mm = -1e30f; for (int w = 0; w < nw; w++) mm = fmaxf(mm, red[w]); bval = mm; }
    __syncthreads();
    m = bval;
    float e = (tid < NS) ? expf(v - m) : 0.f;
    float s = warpSum(e);
    __syncthreads();
    if (lane == 0) red[wid] = s;
    __syncthreads();
    if (tid == 0) { float ss = 0.f; for (int w = 0; w < nw; w++) ss += red[w]; bval = ss; }
    __syncthreads();
    if (tid < NS) g_I[tid] = e / bval;

    if (tid < NS) {
        float x0 = emisk[tid * 4 + 0], x1 = emisk[tid * 4 + 1];
        float x2 = emisk[tid * 4 + 2], x3 = emisk[tid * 4 + 3];
        float mm = fmaxf(fmaxf(x0, x1), fmaxf(x2, x3));
        float e0 = expf(x0 - mm), e1 = expf(x1 - mm), e2 = expf(x2 - mm), e3 = expf(x3 - mm);
        float inv = 1.f / (e0 + e1 + e2 + e3);
        g_BmT[0][tid] = e0 * inv; g_BmT[1][tid] = e1 * inv;
        g_BmT[2][tid] = e2 * inv; g_BmT[3][tid] = e3 * inv;
    }
}

// ---------------- softmax rows of transition -> A16 ----------------
__global__ void k_softA(const float* __restrict__ trans) {
    __shared__ float red[10];
    __shared__ float bval;
    int r = blockIdx.x, tid = threadIdx.x;
    int wid = tid >> 5, lane = tid & 31;
    float v = (tid < NS) ? trans[r * NS + tid] : -1e30f;
    float m = warpMax(v);
    if (lane == 0) red[wid] = m;
    __syncthreads();
    if (tid == 0) { float mm = -1e30f; for (int w = 0; w < 10; w++) mm = fmaxf(mm, red[w]); bval = mm; }
    __syncthreads();
    m = bval;
    float e = (tid < NS) ? expf(v - m) : 0.f;
    float s = warpSum(e);
    __syncthreads();
    if (lane == 0) red[wid] = s;
    __syncthreads();
    if (tid == 0) { float ss = 0.f; for (int w = 0; w < 10; w++) ss += red[w]; bval = ss; }
    __syncthreads();
    if (tid < NS) g_A16[r * SP + tid] = __float2half_rn(e / bval);
}

// ---------------- observation -> 5-gram indices ----------------
__global__ void k_gram(const float* __restrict__ inputs) {
    int b = blockIdx.x;
    const float* inb = inputs + (size_t)b * NT * 4;
    for (int tau = threadIdx.x; tau < NSTEP; tau += blockDim.x) {
        int t0 = 1 + 5 * tau;
        unsigned g = 0;
        #pragma unroll
        for (int k = 0; k < 5; k++) {
            const float* p = inb + (size_t)(t0 + k) * 4;
            float fi = p[1] + 2.f * p[2] + 3.f * p[3];   // exact argmax of one-hot
            g = (g << 2) | (unsigned)(fi + 0.5f);
        }
        g_gram[b * NSTEP + tau] = (unsigned short)g;      // z = g>>2 (8b), fold = g&3
    }
    if (threadIdx.x == 0) {
        const float* p = inb;
        g_o0[b] = (unsigned char)(p[1] + 2.f * p[2] + 3.f * p[3] + 0.5f);
    }
}

// ---------------- wmma fp16 GEMM: C = (L * diag(sc)) @ R, all [320,320] half ----------------
// mode 0: Q_z = (A*Dz)@A (z<4); mode 1: U_z = (Q_{z>>2}*D_{z&3})@A (z<16);
// mode 2: M_z = (Q_{z>>6}*D_{(z>>4)&3})@U_{z&15} (z<256)
__global__ void __launch_bounds__(256) k_gemm_h(int mode) {
    int z = blockIdx.z;
    const __half *Lp, *Rp;
    const float* sc;
    __half* outp;
    if (mode == 0)      { Lp = g_A16;        sc = g_BmT[z];           Rp = g_A16;        outp = g_Q16[z]; }
    else if (mode == 1) { Lp = g_Q16[z >> 2]; sc = g_BmT[z & 3];      Rp = g_A16;        outp = g_U16[z]; }
    else                { Lp = g_Q16[z >> 6]; sc = g_BmT[(z >> 4) & 3]; Rp = g_U16[z & 15]; outp = g_M16 + (size_t)z * SPSP; }
    int m0 = blockIdx.y * 64, n0 = blockIdx.x * 64;

    __shared__ __align__(16) __half As[64][72];
    __shared__ __align__(16) __half Bs[64][72];
    __shared__ __align__(16) float Cs[64][68];

    int tid = threadIdx.x;
    int w = tid >> 5;
    int wm = w & 3, wn = w >> 2;                 // 4 M-blocks x 2 N-blocks (16x32 per warp)
    int lr = tid >> 2, lc = (tid & 3) * 16;

    wmma::fragment<wmma::accumulator, 16, 16, 16, float> cf[2];
    wmma::fill_fragment(cf[0], 0.f);
    wmma::fill_fragment(cf[1], 0.f);

    for (int k0 = 0; k0 < SP; k0 += 64) {
        #pragma unroll
        for (int j = 0; j < 16; j += 2) {
            __half2 lv = *(const __half2*)&Lp[(size_t)(m0 + lr) * SP + k0 + lc + j];
            float2 sv = *(const float2*)&sc[k0 + lc + j];
            float2 lf = __half22float2(lv);
            *(__half2*)&As[lr][lc + j] = __floats2half2_rn(lf.x * sv.x, lf.y * sv.y);
            *(__half2*)&Bs[lr][lc + j] = *(const __half2*)&Rp[(size_t)(k0 + lr) * SP + n0 + lc + j];
        }
        __syncthreads();
        #pragma unroll
        for (int kk = 0; kk < 4; kk++) {
            wmma::fragment<wmma::matrix_a, 16, 16, 16, __half, wmma::row_major> af;
            wmma::load_matrix_sync(af, &As[wm * 16][kk * 16], 72);
            #pragma unroll
            for (int nn = 0; nn < 2; nn++) {
                wmma::fragment<wmma::matrix_b, 16, 16, 16, __half, wmma::row_major> bf;
                wmma::load_matrix_sync(bf, &Bs[kk * 16][wn * 32 + nn * 16], 72);
                wmma::mma_sync(cf[nn], af, bf, cf[nn]);
            }
        }
        __syncthreads();
    }
    wmma::store_matrix_sync(&Cs[wm * 16][wn * 32 + 0], cf[0], 68, wmma::mem_row_major);
    wmma::store_matrix_sync(&Cs[wm * 16][wn * 32 + 16], cf[1], 68, wmma::mem_row_major);
    __syncthreads();
    #pragma unroll
    for (int j = 0; j < 16; j++)
        outp[(size_t)(m0 + lr) * SP + n0 + lc + j] = __float2half_rn(Cs[lr][lc + j]);
}

// ---------------- quantize M to e5m2, warp-per-row, 8-col blocked, 2 dithered copies ----------------
__global__ void k_quant() {
    int z = blockIdx.y, c = blockIdx.z;
    int warp = threadIdx.x >> 5, lane = threadIdx.x & 31;
    int r = blockIdx.x * 8 + warp;
    const __half* row = g_M16 + (size_t)z * SPSP + (size_t)r * SP;

    float vv[10];
    float mx = 0.f;
    #pragma unroll
    for (int i = 0; i < 10; i++) { vv[i] = __half2float(row[lane + 32 * i]); mx = fmaxf(mx, vv[i]); }
    mx = warpMaxAll(mx);
    float q = (mx > 0.f) ? 384.f / mx : 1.f;
    if (c == 1) q *= DITH1;
    unsigned char* dst = g_S + ((size_t)c * NMAT + z) * SPSP;
    int rk = r >> 5, rL = r & 31;
    #pragma unroll
    for (int i = 0; i < 10; i++) {
        int col = lane + 32 * i;
        dst[(((rk * 40 + (col >> 3)) * 32 + rL) << 3) + (col & 7)] =
            (unsigned char)__nv_cvt_float_to_fp8(vv[i] * q, __NV_SATFINITE, __NV_E5M2);
    }
    if (lane == 0) g_rs[(c * NMAT + z) * SP + r] = 4096.f / q;
}

// ================= chain: 2-CTA cluster runs TWO interleaved batches =================
// Grid 64 CTAs = 32 clusters; cluster handles batches (2*cl, 2*cl+1). Per step:
// [compute+publish A] [compute+publish B] [wait A] [wait B] — B's compute hides A's
// sync tail; A's next-step compute hides B's. All per-batch state independent
// (ah2/redp/sg/mbar). Semantics per batch identical to R8/R10 (deferred-si, e5m2+PRMT).

#define PROLOGUE(IB, BIDX, Z0, LLF)                                              \
    {                                                                            \
        int o0 = g_o0[BIDX];                                                     \
        float v0p = (tid < SP) ? g_I[tid] * g_BmT[o0][tid] : 0.f;                \
        float wsum = warpSum(v0p);                                               \
        if (lane == 0) pr[w] = wsum;                                             \
        __syncthreads();                                                         \
        if (tid == 0) {                                                          \
            float x = 0.f;                                                       \
            _Pragma("unroll")                                                    \
            for (int q = 0; q < 20; q++) x += pr[q];                             \
            psinv = 1.f / x;                                                     \
            pr[0] = x;                                                           \
        }                                                                        \
        __syncthreads();                                                         \
        LLF = logf(pr[0]);                                                       \
        if (tid < SP) af[tid] = v0p * psinv;                                     \
        __syncthreads();                                                         \
        if (tid < 160) {                                                         \
            float2 rsv = *(const float2*)&g_rs[(Z0) * SP + 2 * tid];             \
            float a0 = af[2 * tid] * rsv.x, a1 = af[2 * tid + 1] * rsv.y;        \
            ah2[IB][0][2 * tid]     = __floats2half2_rn(a0, a0);                 \
            ah2[IB][0][2 * tid + 1] = __floats2half2_rn(a1, a1);                 \
        }                                                                        \
        __syncthreads();                                                         \
    }

#define DO_BATCH(IB, MBARADDR, LLF, LC, MR)                                      \
    {                                                                            \
        int d = sg[IB][step] & 3;                                                \
        int zn = sg[IB][step + 1] >> 2;                                          \
        int zoff = nb * NMAT + zn;                                               \
        float tot = 0.f;                                                         \
        _Pragma("unroll")                                                        \
        for (int q = 0; q < 10; q++) {                                           \
            float4 t = *(const float4*)&redp[IB][nb][4 * q];                     \
            tot += (t.x + t.y) + (t.z + t.w);                                    \
        }                                                                        \
        float si = __frcp_rn(tot);                                               \
        if (rank == 0 && tid == 0) {                                             \
            float y = logf(tot) - LC;                                            \
            float t2 = LLF + y;                                                  \
            LC = (t2 - LLF) - y;                                                 \
            LLF = t2;                                                            \
        }                                                                        \
        float2 fo  = *(const float2*)&g_BmT[d][gcol];                            \
        float2 rsv = *(const float2*)&g_rs[(size_t)zoff * SP + gcol];            \
        __half2 a0 = __floats2half2_rn(0.f, 0.f), a1 = a0, a2 = a0, a3 = a0;     \
        _Pragma("unroll")                                                        \
        for (int k = 0; k < 10; k++) {                                           \
            __half2 av = ah2[IB][pb][lane + 32 * k];                             \
            a0 = __hfma2(av, u2h(__byte_perm(MR[k].x, 0, 0x1404)), a0);          \
            a1 = __hfma2(av, u2h(__byte_perm(MR[k].x, 0, 0x3424)), a1);          \
            a2 = __hfma2(av, u2h(__byte_perm(MR[k].y, 0, 0x1404)), a2);          \
            a3 = __hfma2(av, u2h(__byte_perm(MR[k].y, 0, 0x3424)), a3);          \
        }                                                                        \
        uint32_t h0 = h2u(a0), h1 = h2u(a1), h2v = h2u(a2), h3 = h2u(a3);        \
        {                                                                        \
            uint32_t g0 = bit0 ? h0 : h1, g1 = bit0 ? h2v : h3;                  \
            uint32_t r0 = __shfl_xor_sync(0xffffffffu, g0, 1);                   \
            uint32_t r1 = __shfl_xor_sync(0xffffffffu, g1, 1);                   \
            h0 = hadd2u(bit0 ? h1 : h0, r0);                                     \
            h1 = hadd2u(bit0 ? h3 : h2v, r1);                                    \
        }                                                                        \
        {                                                                        \
            uint32_t g0 = bit1 ? h0 : h1;                                        \
            uint32_t r0 = __shfl_xor_sync(0xffffffffu, g0, 2);                   \
            h0 = hadd2u(bit1 ? h1 : h0, r0);                                     \
        }                                                                        \
        h0 = hadd2u(h0, __shfl_xor_sync(0xffffffffu, h0, 4));                    \
        h0 = hadd2u(h0, __shfl_xor_sync(0xffffffffu, h0, 8));                    \
        h0 = hadd2u(h0, __shfl_xor_sync(0xffffffffu, h0, 16));                   \
        float p = 0.f;                                                           \
        if (lane < 4) {                                                          \
            float2 f2 = __half22float2(u2h(h0));                                 \
            float v0 = f2.x * fo.x * si, v1 = f2.y * fo.y * si;                  \
            float b0v = v0 * rsv.x, b1v = v1 * rsv.y;                            \
            uint32_t pkx = h2u(__floats2half2_rn(b0v, b0v));                     \
            uint32_t pky = h2u(__floats2half2_rn(b1v, b1v));                     \
            *(uint2*)&ah2[IB][nb][gcol] = make_uint2(pkx, pky);                  \
            uint64_t vv = ((uint64_t)pky << 32) | pkx;                           \
            uint32_t la = s2u(&ah2[IB][nb][gcol]);                               \
            asm volatile(                                                        \
                "{ .reg .b32 ra; mapa.shared::cluster.u32 ra, %0, %1;"           \
                "  st.shared::cluster.b64 [ra], %2; }"                           \
                :: "r"(la), "r"(peer), "l"(vv) : "memory");                      \
            p = v0 + v1;                                                         \
        }                                                                        \
        p += __shfl_xor_sync(0xffffffffu, p, 1);                                 \
        p += __shfl_xor_sync(0xffffffffu, p, 2);                                 \
        if (lane == 0) {                                                         \
            redp[IB][pb][slot] = p;                                              \
            uint32_t la = s2u(&redp[IB][pb][slot]);                              \
            asm volatile(                                                        \
                "{ .reg .b32 ra; mapa.shared::cluster.u32 ra, %0, %1;"           \
                "  st.shared::cluster.b32 [ra], %2; }"                           \
                :: "r"(la), "r"(peer), "f"(p) : "memory");                       \
        }                                                                        \
        if (lane < 4) {                                                          \
            asm volatile(                                                        \
                "{ .reg .b32 ra; mapa.shared::cluster.u32 ra, %0, %1;"           \
                "  mbarrier.arrive.shared::cluster.b64 _, [ra]; }"               \
                :: "r"(MBARADDR), "r"(peer) : "memory");                         \
        }                                                                        \
        asm volatile("mbarrier.arrive.shared.b64 _, [%0];" :: "r"(MBARADDR) : "memory"); \
        {                                                                        \
            const uint2* base = (const uint2*)(g_S + (size_t)zoff * SPSP);       \
            _Pragma("unroll")                                                    \
            for (int k = 0; k < 10; k++) MR[k] = __ldcg(base + (k * 40 + cb) * 32 + lane); \
        }                                                                        \
    }

#define MBAR_WAIT(MBARADDR, PAR)                                                 \
    {                                                                            \
        uint32_t done;                                                           \
        asm volatile(                                                            \
            "{ .reg .pred P;"                                                    \
            "  mbarrier.try_wait.parity.acquire.cluster.shared::cta.b64 P, [%1], %2;" \
            "  selp.b32 %0, 1, 0, P; }"                                          \
            : "=r"(done) : "r"(MBARADDR), "r"(PAR) : "memory");                  \
        if (!done) {                                                             \
            asm volatile(                                                        \
                "{ .reg .pred P;"                                                \
                "WL_%=:"                                                         \
                "  mbarrier.try_wait.parity.acquire.cluster.shared::cta.b64 P, [%0], %1, 0x989680;" \
                "  @P bra WD_%=;"                                                \
                "  bra WL_%=;"                                                   \
                "WD_%=: }"                                                       \
                :: "r"(MBARADDR), "r"(PAR) : "memory");                          \
        }                                                                        \
    }

__global__ void __launch_bounds__(640, 1) __cluster_dims__(2, 1, 1)
k_chain(float* __restrict__ out) {
    int tid = threadIdx.x;
    int bp = blockIdx.x >> 1;                     // cluster index 0..31
    int bA = bp * 2, bB = bA + 1;
    uint32_t rank;
    asm("mov.u32 %0, %%cluster_ctarank;" : "=r"(rank));
    int peer = 1 - (int)rank;

    __shared__ __half2 ah2[2][2][SP];             // [batch][buf][state]
    __shared__ __align__(16) float redp[2][2][48];
    __shared__ unsigned short sg[2][NSTEP + 1];
    __shared__ __align__(8) uint64_t mbar[2];
    __shared__ float pr[20];
    __shared__ float psinv;
    __shared__ float af[SP];

    int lane = tid & 31, w = tid >> 5;
    uint32_t mbA = s2u(&mbar[0]);
    uint32_t mbB = s2u(&mbar[1]);

    for (int i = tid; i < NSTEP; i += 640) {
        sg[0][i] = g_gram[bA * NSTEP + i];
        sg[1][i] = g_gram[bB * NSTEP + i];
    }
    if (tid == 0) { sg[0][NSTEP] = 0; sg[1][NSTEP] = 0; }
    if (tid < 48) {
        redp[0][0][tid] = 0.f; redp[0][1][tid] = (tid == 0) ? 1.f : 0.f;
        redp[1][0][tid] = 0.f; redp[1][1][tid] = (tid == 0) ? 1.f : 0.f;
    }
    if (tid == 0) {
        asm volatile("mbarrier.init.shared.b64 [%0], %1;" :: "r"(mbA), "r"(720) : "memory");
        asm volatile("mbarrier.init.shared.b64 [%0], %1;" :: "r"(mbB), "r"(720) : "memory");
    }
    __syncthreads();
    asm volatile("barrier.cluster.arrive.aligned;" ::: "memory");
    asm volatile("barrier.cluster.wait.aligned;" ::: "memory");

    int z0A = sg[0][0] >> 2, z0B = sg[1][0] >> 2;
    float llfA = 0.f, lcA = 0.f, llfB = 0.f, lcB = 0.f;

    PROLOGUE(0, bA, z0A, llfA)
    PROLOGUE(1, bB, z0B, llfB)

    int cb = (int)rank * 20 + w;
    int gcol = (int)rank * 160 + 8 * w + 2 * (lane & 3);
    int slot = (int)rank * 20 + w;
    int bit0 = lane & 1, bit1 = (lane >> 1) & 1;

    uint2 mrA[10], mrB[10];
    {
        const uint2* baseA = (const uint2*)(g_S + (size_t)z0A * SPSP);
        const uint2* baseB = (const uint2*)(g_S + (size_t)z0B * SPSP);
        #pragma unroll
        for (int k = 0; k < 10; k++) {
            mrA[k] = __ldcg(baseA + (k * 40 + cb) * 32 + lane);
            mrB[k] = __ldcg(baseB + (k * 40 + cb) * 32 + lane);
        }
    }

    for (int step = 0; step < NSTEP; ++step) {
        int pb = step & 1, nb = 1 - pb;
        uint32_t parity = (uint32_t)(step & 1);

        DO_BATCH(0, mbA, llfA, lcA, mrA)
        DO_BATCH(1, mbB, llfB, lcB, mrB)
        MBAR_WAIT(mbA, parity)
        MBAR_WAIT(mbB, parity)
    }

    if (rank == 0 && tid == 0) {
        int fb = (NSTEP - 1) & 1;
        float totA = 0.f, totB = 0.f;
        #pragma unroll
        for (int q = 0; q < 40; q++) { totA += redp[0][fb][q]; totB += redp[1][fb][q]; }
        llfA += logf(totA);
        llfB += logf(totB);
        out[bA] = (float)((double)llfA - (double)NSTEP * LOG_SCALE_D);
        out[bB] = (float)((double)llfB - (double)NSTEP * LOG_SCALE_D);
    }
}

// ---------------- launch ----------------
extern "C" void kernel_launch(void* const* d_in, const int* in_sizes, int n_in,
                              void* d_out, int out_size) {
    const float* inputs = (const float*)d_in[0];
    const float* initk  = (const float*)d_in[1];
    const float* transk = (const float*)d_in[2];
    const float* emisk  = (const float*)d_in[3];
    float* out = (float*)d_out;

    k_setup<<<1, 512>>>(initk, emisk);
    k_softA<<<NS, 320>>>(transk);
    k_gram<<<NB, 256>>>(inputs);
    k_gemm_h<<<dim3(5, 5, 4), 256>>>(0);     // Q_a
    k_gemm_h<<<dim3(5, 5, 16), 256>>>(1);    // U_cd
    k_gemm_h<<<dim3(5, 5, 256), 256>>>(2);   // M_abcd
    k_quant<<<dim3(40, 256, 2), 256>>>();
    k_chain<<<NB, 640>>>(out);               // 64 CTAs = 32 clusters x 2 batches
}

// round 12
// speedup vs baseline: 1.5452x; 1.5452x over previous
#include <cuda_runtime.h>
#include <cuda_fp16.h>
#include <cuda_fp8.h>
#include <mma.h>
#include <math.h>
#include <stdint.h>

using namespace nvcuda;

#define NS 305
#define SP 320
#define SPSP (SP * SP)
#define NB 64
#define NT 4096
#define NSTEP 819            // 5-gram supersteps: 1 + 5*819 = 4096 exactly
#define NMAT 256             // 4^4 composite matrices
#define LOG_SCALE_D 8.317766166719343   // log(4096)
#define DITH1 1.0471f        // dither factor for copy 1 (compensated exactly via g_rs)

// ---------------- device globals (zero-initialized) ----------------
__device__ float g_I[SP];
__device__ __align__(16) float g_BmT[4][SP];              // BmT[a][s] = Bm[s][a]
__device__ __align__(16) __half g_A16[SPSP];              // softmax(A), fp16
__device__ __align__(16) __half g_Q16[4][SPSP];           // Q_a = (A Da) A
__device__ __align__(16) __half g_U16[16][SPSP];          // U_cd = (Q_c Dd) A
__device__ __align__(16) __half g_M16[(size_t)NMAT * SPSP];  // M_abcd = (Q_a Db) U_cd
// e5m2, 2 dither copies, 8-col blocked: byte (r,c) at ((r>>5)*40 + (c>>3))*256 + (r&31)*8 + (c&7)
__device__ __align__(16) unsigned char g_S[2ull * NMAT * SPSP];
__device__ __align__(16) float g_rs[2 * NMAT * SP];       // alpha row multiplier 4096/q per copy
__device__ unsigned short g_gram[NB * NSTEP];             // (z<<2)|fold, z in 0..255
__device__ unsigned char g_o0[NB];

__device__ __forceinline__ float warpSum(float x) {
    #pragma unroll
    for (int o = 16; o; o >>= 1) x += __shfl_down_sync(0xffffffffu, x, o);
    return x;
}
__device__ __forceinline__ float warpMax(float x) {
    #pragma unroll
    for (int o = 16; o; o >>= 1) x = fmaxf(x, __shfl_down_sync(0xffffffffu, x, o));
    return x;
}
__device__ __forceinline__ float warpMaxAll(float x) {
    #pragma unroll
    for (int o = 16; o; o >>= 1) x = fmaxf(x, __shfl_xor_sync(0xffffffffu, x, o));
    return x;
}
__device__ __forceinline__ __half2 u2h(uint32_t u) { return *reinterpret_cast<__half2*>(&u); }
__device__ __forceinline__ uint32_t h2u(__half2 h) { return *reinterpret_cast<uint32_t*>(&h); }
__device__ __forceinline__ uint32_t hadd2u(uint32_t a, uint32_t b) {
    return h2u(__hadd2(u2h(a), u2h(b)));
}
__device__ __forceinline__ uint32_t s2u(const void* p) {
    uint32_t a;
    asm("{ .reg .u64 t; cvta.to.shared.u64 t, %1; cvt.u32.u64 %0, t; }" : "=r"(a) : "l"(p));
    return a;
}

// ---------------- setup: I softmax + emission softmax ----------------
__global__ void k_setup(const float* __restrict__ initk, const float* __restrict__ emisk) {
    __shared__ float red[16];
    __shared__ float bval;
    int tid = threadIdx.x, wid = tid >> 5, lane = tid & 31;
    const int nw = 16;
    float v = (tid < NS) ? initk[tid] : -1e30f;
    float m = warpMax(v);
    if (lane == 0) red[wid] = m;
    __syncthreads();
    if (tid == 0) { float mm = -1e30f; for (int w = 0; w < nw; w++) mm = fmaxf(mm, red[w]); bval = mm; }
    __syncthreads();
    m = bval;
    float e = (tid < NS) ? expf(v - m) : 0.f;
    float s = warpSum(e);
    __syncthreads();
    if (lane == 0) red[wid] = s;
    __syncthreads();
    if (tid == 0) { float ss = 0.f; for (int w = 0; w < nw; w++) ss += red[w]; bval = ss; }
    __syncthreads();
    if (tid < NS) g_I[tid] = e / bval;

    if (tid < NS) {
        float x0 = emisk[tid * 4 + 0], x1 = emisk[tid * 4 + 1];
        float x2 = emisk[tid * 4 + 2], x3 = emisk[tid * 4 + 3];
        float mm = fmaxf(fmaxf(x0, x1), fmaxf(x2, x3));
        float e0 = expf(x0 - mm), e1 = expf(x1 - mm), e2 = expf(x2 - mm), e3 = expf(x3 - mm);
        float inv = 1.f / (e0 + e1 + e2 + e3);
        g_BmT[0][tid] = e0 * inv; g_BmT[1][tid] = e1 * inv;
        g_BmT[2][tid] = e2 * inv; g_BmT[3][tid] = e3 * inv;
    }
}

// ---------------- softmax rows of transition -> A16 ----------------
__global__ void k_softA(const float* __restrict__ trans) {
    __shared__ float red[10];
    __shared__ float bval;
    int r = blockIdx.x, tid = threadIdx.x;
    int wid = tid >> 5, lane = tid & 31;
    float v = (tid < NS) ? trans[r * NS + tid] : -1e30f;
    float m = warpMax(v);
    if (lane == 0) red[wid] = m;
    __syncthreads();
    if (tid == 0) { float mm = -1e30f; for (int w = 0; w < 10; w++) mm = fmaxf(mm, red[w]); bval = mm; }
    __syncthreads();
    m = bval;
    float e = (tid < NS) ? expf(v - m) : 0.f;
    float s = warpSum(e);
    __syncthreads();
    if (lane == 0) red[wid] = s;
    __syncthreads();
    if (tid == 0) { float ss = 0.f; for (int w = 0; w < 10; w++) ss += red[w]; bval = ss; }
    __syncthreads();
    if (tid < NS) g_A16[r * SP + tid] = __float2half_rn(e / bval);
}

// ---------------- observation -> 5-gram indices ----------------
__global__ void k_gram(const float* __restrict__ inputs) {
    int b = blockIdx.x;
    const float* inb = inputs + (size_t)b * NT * 4;
    for (int tau = threadIdx.x; tau < NSTEP; tau += blockDim.x) {
        int t0 = 1 + 5 * tau;
        unsigned g = 0;
        #pragma unroll
        for (int k = 0; k < 5; k++) {
            const float* p = inb + (size_t)(t0 + k) * 4;
            float fi = p[1] + 2.f * p[2] + 3.f * p[3];   // exact argmax of one-hot
            g = (g << 2) | (unsigned)(fi + 0.5f);
        }
        g_gram[b * NSTEP + tau] = (unsigned short)g;      // z = g>>2 (8b), fold = g&3
    }
    if (threadIdx.x == 0) {
        const float* p = inb;
        g_o0[b] = (unsigned char)(p[1] + 2.f * p[2] + 3.f * p[3] + 0.5f);
    }
}

// ---------------- wmma fp16 GEMM: C = (L * diag(sc)) @ R, all [320,320] half ----------------
// mode 0: Q_z = (A*Dz)@A (z<4); mode 1: U_z = (Q_{z>>2}*D_{z&3})@A (z<16);
// mode 2: M_z = (Q_{z>>6}*D_{(z>>4)&3})@U_{z&15} (z<256)
__global__ void __launch_bounds__(256) k_gemm_h(int mode) {
    int z = blockIdx.z;
    const __half *Lp, *Rp;
    const float* sc;
    __half* outp;
    if (mode == 0)      { Lp = g_A16;        sc = g_BmT[z];           Rp = g_A16;        outp = g_Q16[z]; }
    else if (mode == 1) { Lp = g_Q16[z >> 2]; sc = g_BmT[z & 3];      Rp = g_A16;        outp = g_U16[z]; }
    else                { Lp = g_Q16[z >> 6]; sc = g_BmT[(z >> 4) & 3]; Rp = g_U16[z & 15]; outp = g_M16 + (size_t)z * SPSP; }
    int m0 = blockIdx.y * 64, n0 = blockIdx.x * 64;

    __shared__ __align__(16) __half As[64][72];
    __shared__ __align__(16) __half Bs[64][72];
    __shared__ __align__(16) float Cs[64][68];

    int tid = threadIdx.x;
    int w = tid >> 5;
    int wm = w & 3, wn = w >> 2;                 // 4 M-blocks x 2 N-blocks (16x32 per warp)
    int lr = tid >> 2, lc = (tid & 3) * 16;

    wmma::fragment<wmma::accumulator, 16, 16, 16, float> cf[2];
    wmma::fill_fragment(cf[0], 0.f);
    wmma::fill_fragment(cf[1], 0.f);

    for (int k0 = 0; k0 < SP; k0 += 64) {
        #pragma unroll
        for (int j = 0; j < 16; j += 2) {
            __half2 lv = *(const __half2*)&Lp[(size_t)(m0 + lr) * SP + k0 + lc + j];
            float2 sv = *(const float2*)&sc[k0 + lc + j];
            float2 lf = __half22float2(lv);
            *(__half2*)&As[lr][lc + j] = __floats2half2_rn(lf.x * sv.x, lf.y * sv.y);
            *(__half2*)&Bs[lr][lc + j] = *(const __half2*)&Rp[(size_t)(k0 + lr) * SP + n0 + lc + j];
        }
        __syncthreads();
        #pragma unroll
        for (int kk = 0; kk < 4; kk++) {
            wmma::fragment<wmma::matrix_a, 16, 16, 16, __half, wmma::row_major> af;
            wmma::load_matrix_sync(af, &As[wm * 16][kk * 16], 72);
            #pragma unroll
            for (int nn = 0; nn < 2; nn++) {
                wmma::fragment<wmma::matrix_b, 16, 16, 16, __half, wmma::row_major> bf;
                wmma::load_matrix_sync(bf, &Bs[kk * 16][wn * 32 + nn * 16], 72);
                wmma::mma_sync(cf[nn], af, bf, cf[nn]);
            }
        }
        __syncthreads();
    }
    wmma::store_matrix_sync(&Cs[wm * 16][wn * 32 + 0], cf[0], 68, wmma::mem_row_major);
    wmma::store_matrix_sync(&Cs[wm * 16][wn * 32 + 16], cf[1], 68, wmma::mem_row_major);
    __syncthreads();
    #pragma unroll
    for (int j = 0; j < 16; j++)
        outp[(size_t)(m0 + lr) * SP + n0 + lc + j] = __float2half_rn(Cs[lr][lc + j]);
}

// ---------------- quantize M to e5m2, warp-per-row, 8-col blocked, 2 dithered copies ----------------
__global__ void k_quant() {
    int z = blockIdx.y, c = blockIdx.z;
    int warp = threadIdx.x >> 5, lane = threadIdx.x & 31;
    int r = blockIdx.x * 8 + warp;
    const __half* row = g_M16 + (size_t)z * SPSP + (size_t)r * SP;

    float vv[10];
    float mx = 0.f;
    #pragma unroll
    for (int i = 0; i < 10; i++) { vv[i] = __half2float(row[lane + 32 * i]); mx = fmaxf(mx, vv[i]); }
    mx = warpMaxAll(mx);
    float q = (mx > 0.f) ? 384.f / mx : 1.f;
    if (c == 1) q *= DITH1;
    unsigned char* dst = g_S + ((size_t)c * NMAT + z) * SPSP;
    int rk = r >> 5, rL = r & 31;
    #pragma unroll
    for (int i = 0; i < 10; i++) {
        int col = lane + 32 * i;
        dst[(((rk * 40 + (col >> 3)) * 32 + rL) << 3) + (col & 7)] =
            (unsigned char)__nv_cvt_float_to_fp8(vv[i] * q, __NV_SATFINITE, __NV_E5M2);
    }
    if (lane == 0) g_rs[(c * NMAT + z) * SP + r] = 4096.f / q;
}

// ---------------- chain: 2-CTA cluster per batch, full-step mr prefetch + log ring ----------------
// R10 structure; two changes:
//  (1) step+1's matrix loads issue at the TOP of each step into mrN (full step of latency
//      cover); FMA uses mr; after the mbar wait, mr <- mrN (register moves).
//  (2) per-step logf replaced by a ring: tid0 stores tot (1 STS); warp0 flushes 32 logfs
//      in parallel every 32 steps; epilogue drains the remainder.
__global__ void __launch_bounds__(640, 1) __cluster_dims__(2, 1, 1)
k_chain(float* __restrict__ out) {
    int tid = threadIdx.x;
    int b = blockIdx.x >> 1;
    uint32_t rank;
    asm("mov.u32 %0, %%cluster_ctarank;" : "=r"(rank));
    int peer = 1 - (int)rank;

    __shared__ __half2 ah2[2][SP];
    __shared__ __align__(16) float redp[2][48];    // slots 0..39 used (rank*20 + w)
    __shared__ unsigned short sg[NSTEP + 1];
    __shared__ float ring[32];
    __shared__ __align__(8) uint64_t mbar;
    __shared__ float pr[20];
    __shared__ float psinv;
    __shared__ float af[SP];

    int lane = tid & 31, w = tid >> 5;
    uint32_t mbarA = s2u(&mbar);

    for (int i = tid; i < NSTEP; i += 640) sg[i] = g_gram[b * NSTEP + i];
    int o0 = g_o0[b];
    if (tid == 0) sg[NSTEP] = 0;                   // sentinel for step+1 lookahead
    if (tid < 48) { redp[0][tid] = 0.f; redp[1][tid] = (tid == 0) ? 1.f : 0.f; }
    if (tid == 0)
        asm volatile("mbarrier.init.shared.b64 [%0], %1;" :: "r"(mbarA), "r"(720) : "memory");
    __syncthreads();
    asm volatile("barrier.cluster.arrive.aligned;" ::: "memory");
    asm volatile("barrier.cluster.wait.aligned;" ::: "memory");

    int z0 = sg[0] >> 2;

    // ---- prologue: both CTAs build the FULL normalized alpha0 ----
    float llf = 0.f;
    {
        float v0p = (tid < SP) ? g_I[tid] * g_BmT[o0][tid] : 0.f;
        float wsum = warpSum(v0p);
        if (lane == 0) pr[w] = wsum;
        __syncthreads();
        if (tid == 0) {
            float x = 0.f;
            #pragma unroll
            for (int q = 0; q < 20; q++) x += pr[q];
            psinv = 1.f / x;
            pr[0] = x;
        }
        __syncthreads();
        llf = logf(pr[0]);
        if (tid < SP) af[tid] = v0p * psinv;
        __syncthreads();
        if (tid < 160) {
            float2 rsv = *(const float2*)&g_rs[z0 * SP + 2 * tid];   // step 0 = copy 0
            float a0 = af[2 * tid] * rsv.x, a1 = af[2 * tid + 1] * rsv.y;
            ah2[0][2 * tid]     = __floats2half2_rn(a0, a0);
            ah2[0][2 * tid + 1] = __floats2half2_rn(a1, a1);
        }
        __syncthreads();
    }

    int cb = (int)rank * 20 + w;                   // 8-col block index owned by this warp
    int gcol = (int)rank * 160 + 8 * w + 2 * (lane & 3);
    int slot = (int)rank * 20 + w;
    int bit0 = lane & 1, bit1 = (lane >> 1) & 1;

    // ---- preload mr for step 0 (copy 0) ----
    uint2 mr[10], mrN[10];
    {
        const uint2* base = (const uint2*)(g_S + (size_t)z0 * SPSP);
        #pragma unroll
        for (int k = 0; k < 10; k++) mr[k] = __ldcg(base + (k * 40 + cb) * 32 + lane);
    }

    for (int step = 0; step < NSTEP; ++step) {
        int pb = step & 1, nb = 1 - pb;
        int d = sg[step] & 3;
        int zn = sg[step + 1] >> 2;                // sentinel makes last lookahead safe
        int zoff = nb * NMAT + zn;                 // dither copy alternates by step

        // ---- (1) issue step+1's matrix loads FIRST: a full step of latency cover ----
        {
            const uint2* base = (const uint2*)(g_S + (size_t)zoff * SPSP);
            #pragma unroll
            for (int k = 0; k < 10; k++) mrN[k] = __ldcg(base + (k * 40 + cb) * 32 + lane);
        }

        // si_prev from last step's 40 global partials
        float tot = 0.f;
        #pragma unroll
        for (int q = 0; q < 10; q++) {
            float4 t = *(const float4*)&redp[nb][4 * q];
            tot += (t.x + t.y) + (t.z + t.w);
        }
        float si = __frcp_rn(tot);
        // ---- (2) log ring: stash tot; batch-flush 32 logfs on warp0 every 32 steps ----
        if (rank == 0) {
            if (tid == 0) ring[step & 31] = tot;
            if (w == 0 && (step & 31) == 31) {
                __syncwarp();
                float x = logf(ring[lane]);
                x = warpSum(x);
                if (lane == 0) llf += x;
            }
        }
        float2 fo  = *(const float2*)&g_BmT[d][gcol];
        float2 rsv = *(const float2*)&g_rs[(size_t)zoff * SP + gcol];

        // ---- FMA phase: 8 cols, rows lane+32k (uses mr, loaded a full step ago) ----
        __half2 a0 = __floats2half2_rn(0.f, 0.f);
        __half2 a1 = a0, a2 = a0, a3 = a0;
        #pragma unroll
        for (int k = 0; k < 10; k++) {
            __half2 av = ah2[pb][lane + 32 * k];
            a0 = __hfma2(av, u2h(__byte_perm(mr[k].x, 0, 0x1404)), a0);
            a1 = __hfma2(av, u2h(__byte_perm(mr[k].x, 0, 0x3424)), a1);
            a2 = __hfma2(av, u2h(__byte_perm(mr[k].y, 0, 0x1404)), a2);
            a3 = __hfma2(av, u2h(__byte_perm(mr[k].y, 0, 0x3424)), a3);
        }

        // ---- in-warp reduce: lane ends holding col-pair (lane&3) total ----
        uint32_t h0 = h2u(a0), h1 = h2u(a1), h2v = h2u(a2), h3 = h2u(a3);
        {
            uint32_t g0 = bit0 ? h0 : h1, g1 = bit0 ? h2v : h3;
            uint32_t r0 = __shfl_xor_sync(0xffffffffu, g0, 1);
            uint32_t r1 = __shfl_xor_sync(0xffffffffu, g1, 1);
            h0 = hadd2u(bit0 ? h1 : h0, r0);
            h1 = hadd2u(bit0 ? h3 : h2v, r1);
        }
        {
            uint32_t g0 = bit1 ? h0 : h1;
            uint32_t r0 = __shfl_xor_sync(0xffffffffu, g0, 2);
            h0 = hadd2u(bit1 ? h1 : h0, r0);
        }
        h0 = hadd2u(h0, __shfl_xor_sync(0xffffffffu, h0, 4));
        h0 = hadd2u(h0, __shfl_xor_sync(0xffffffffu, h0, 8));
        h0 = hadd2u(h0, __shfl_xor_sync(0xffffffffu, h0, 16));

        // ---- lanes 0-3: finish own 2 cols, write local + remote alpha ----
        float p = 0.f;
        if (lane < 4) {
            float2 f2 = __half22float2(u2h(h0));
            float v0 = f2.x * fo.x * si, v1 = f2.y * fo.y * si;
            float b0 = v0 * rsv.x, b1 = v1 * rsv.y;   // next alpha, un-si'd (deferred)
            uint32_t pkx = h2u(__floats2half2_rn(b0, b0));
            uint32_t pky = h2u(__floats2half2_rn(b1, b1));
            *(uint2*)&ah2[nb][gcol] = make_uint2(pkx, pky);
            uint64_t vv = ((uint64_t)pky << 32) | pkx;
            uint32_t la = s2u(&ah2[nb][gcol]);
            asm volatile(
                "{ .reg .b32 ra; mapa.shared::cluster.u32 ra, %0, %1;"
                "  st.shared::cluster.b64 [ra], %2; }"
                :: "r"(la), "r"(peer), "l"(vv) : "memory");
            p = v0 + v1;
        }
        p += __shfl_xor_sync(0xffffffffu, p, 1);
        p += __shfl_xor_sync(0xffffffffu, p, 2);
        if (lane == 0) {
            redp[pb][slot] = p;
            uint32_t la = s2u(&redp[pb][slot]);
            asm volatile(
                "{ .reg .b32 ra; mapa.shared::cluster.u32 ra, %0, %1;"
                "  st.shared::cluster.b32 [ra], %2; }"
                :: "r"(la), "r"(peer), "f"(p) : "memory");
        }
        if (lane < 4) {
            asm volatile(
                "{ .reg .b32 ra; mapa.shared::cluster.u32 ra, %0, %1;"
                "  mbarrier.arrive.shared::cluster.b64 _, [ra]; }"
                :: "r"(mbarA), "r"(peer) : "memory");
        }
        asm volatile("mbarrier.arrive.shared.b64 _, [%0];" :: "r"(mbarA) : "memory");

        // ---- wait for phase completion (720 arrives), cluster-acquire ----
        {
            uint32_t parity = (uint32_t)(step & 1);
            uint32_t done;
            asm volatile(
                "{ .reg .pred P;"
                "  mbarrier.try_wait.parity.acquire.cluster.shared::cta.b64 P, [%1], %2;"
                "  selp.b32 %0, 1, 0, P; }"
                : "=r"(done) : "r"(mbarA), "r"(parity) : "memory");
            if (!done) {
                asm volatile(
                    "{ .reg .pred P;"
                    "WL_%=:"
                    "  mbarrier.try_wait.parity.acquire.cluster.shared::cta.b64 P, [%0], %1, 0x989680;"
                    "  @P bra WD_%=;"
                    "  bra WL_%=;"
                    "WD_%=: }"
                    :: "r"(mbarA), "r"(parity) : "memory");
            }
        }

        // ---- rotate prefetched matrix into place ----
        #pragma unroll
        for (int k = 0; k < 10; k++) mr[k] = mrN[k];
    }

    // Epilogue: drain ring (steps 800..818 stored s_799..s_817 at ring[0..18]),
    // then the final total s_818 from redp.
    if (rank == 0 && w == 0) {
        float x = (lane < ((NSTEP - 1) & 31) + 1) ? logf(ring[lane]) : 0.f;
        x = warpSum(x);
        if (tid == 0) {
            int fb = (NSTEP - 1) & 1;
            float tot = 0.f;
            #pragma unroll
            for (int q = 0; q < 40; q++) tot += redp[fb][q];
            llf += x + logf(tot);
            out[b] = (float)((double)llf - (double)NSTEP * LOG_SCALE_D);
        }
    }
}

// ---------------- launch ----------------
extern "C" void kernel_launch(void* const* d_in, const int* in_sizes, int n_in,
                              void* d_out, int out_size) {
    const float* inputs = (const float*)d_in[0];
    const float* initk  = (const float*)d_in[1];
    const float* transk = (const float*)d_in[2];
    const float* emisk  = (const float*)d_in[3];
    float* out = (float*)d_out;

    k_setup<<<1, 512>>>(initk, emisk);
    k_softA<<<NS, 320>>>(transk);
    k_gram<<<NB, 256>>>(inputs);
    k_gemm_h<<<dim3(5, 5, 4), 256>>>(0);     // Q_a
    k_gemm_h<<<dim3(5, 5, 16), 256>>>(1);    // U_cd
    k_gemm_h<<<dim3(5, 5, 256), 256>>>(2);   // M_abcd
    k_quant<<<dim3(40, 256, 2), 256>>>();
    k_chain<<<NB * 2, 640>>>(out);
}